// round 10
// baseline (speedup 1.0000x reference)
#include <cuda_runtime.h>
#include <cuda_fp16.h>
#include <cstdint>

// out[e] = sum_d |x[r[e],d] - x[c[e],d]| * w[d] + b[0]
// N_NODES=100000, N_EDGES=600000, D=128 (indices int32: jax x64 disabled)
//
// R9 postmortem: total runtime == total LTS bytes / 6300B-per-cyc cap.
// Only traffic reduction helps. Pipeline:
//   1) convert: fp32 -> fp16 node table (77MB LTS, ~6.4us)
//   2) zero bucket counters
//   3) scatter: counting-bucket edges by r>>5 (32-node buckets) so each
//      gather warp's r-rows span 8KB -> r-side gathers hit L1 instead of L2
//      (saves ~125MB of L2 traffic). Overflow (>320 edges/bucket, ~9-sigma,
//      never in practice) computed inline in fp32 for exactness.
//   4) gather: per-warp 32 same-bucket edges, 16 lanes/edge, half2 math
//      (bit-identical to R8 -> rel_err 7.6e-4), scattered store to out[eid].

#define D_FEAT       128
#define MAX_NODES    100000
#define BUCKET_SHIFT 5
#define NB           3125            // ceil(100000 / 32)
#define CAP          320             // slots/bucket (mean 192), mult of 32
#define NSLOTS       (NB * CAP)      // 1,000,000

// fp16 node table: 100000 rows x 128 halves = 16 uint4 per row (256B rows).
__device__ __align__(256) uint4 g_xh[MAX_NODES * (D_FEAT / 8)];
__device__ int g_cnt[NB];
__device__ int g_sr[NSLOTS];
__device__ int g_sc[NSLOTS];
__device__ int g_se[NSLOTS];

__global__ __launch_bounds__(256)
void convert_fp16_kernel(const float* __restrict__ x, int n_vec)
{
    const int i = blockIdx.x * blockDim.x + threadIdx.x;
    if (i >= n_vec) return;

    const float4* xf = reinterpret_cast<const float4*>(x);
    const float4 f0 = __ldg(xf + 2 * i);
    const float4 f1 = __ldg(xf + 2 * i + 1);

    const __half2 h0 = __floats2half2_rn(f0.x, f0.y);
    const __half2 h1 = __floats2half2_rn(f0.z, f0.w);
    const __half2 h2 = __floats2half2_rn(f1.x, f1.y);
    const __half2 h3 = __floats2half2_rn(f1.z, f1.w);

    uint4 o;
    o.x = *reinterpret_cast<const unsigned int*>(&h0);
    o.y = *reinterpret_cast<const unsigned int*>(&h1);
    o.z = *reinterpret_cast<const unsigned int*>(&h2);
    o.w = *reinterpret_cast<const unsigned int*>(&h3);
    g_xh[i] = o;
}

__global__ void zero_cnt_kernel()
{
    const int i = blockIdx.x * blockDim.x + threadIdx.x;
    if (i < NB) g_cnt[i] = 0;
}

__global__ __launch_bounds__(256)
void scatter_kernel(const int* __restrict__ r_idx,
                    const int* __restrict__ c_idx,
                    const float* __restrict__ x,
                    const float* __restrict__ w,
                    const float* __restrict__ bia,
                    float* __restrict__ out,
                    int n_edges, int n_nodes)
{
    const int i = blockIdx.x * blockDim.x + threadIdx.x;
    if (i >= n_edges) return;

    int r = __ldg(r_idx + i);
    int c = __ldg(c_idx + i);
    r = min(max(r, 0), n_nodes - 1);
    c = min(max(c, 0), n_nodes - 1);

    const int b = r >> BUCKET_SHIFT;
    const int p = atomicAdd(&g_cnt[b], 1);
    if (p < CAP) {
        const int idx = b * CAP + p;
        g_sr[idx] = r;
        g_sc[idx] = c;
        g_se[idx] = i;
    } else {
        // Exact fp32 fallback (statistically unreachable: ~9 sigma).
        float s = 0.0f;
        for (int d = 0; d < D_FEAT; ++d)
            s = fmaf(fabsf(__ldg(x + (size_t)r * D_FEAT + d) -
                           __ldg(x + (size_t)c * D_FEAT + d)),
                     __ldg(w + d), s);
        out[i] = s + __ldg(bia);
    }
}

__device__ __forceinline__ __half2 u2h(unsigned int u)
{
    return *reinterpret_cast<const __half2*>(&u);
}

__global__ __launch_bounds__(256)
void edge_abs_dot_kernel(const float* __restrict__ w,
                         const float* __restrict__ bia,
                         float* __restrict__ out)
{
    const int lane  = threadIdx.x & 31;
    const int g     = lane >> 4;        // group 0..1 (one edge each)
    const int t     = lane & 15;        // position within group
    const int gwarp = (blockIdx.x * blockDim.x + threadIdx.x) >> 5;
    const int slot_base = gwarp << 5;   // 32 slots (same bucket: CAP%32==0)
    if (slot_base >= NSLOTS) return;

    const int b   = slot_base / CAP;
    const int k   = slot_base - b * CAP;
    int cnt = g_cnt[b];
    if (cnt > CAP) cnt = CAP;
    const int nvalid = cnt - k;         // warp-uniform
    if (nvalid <= 0) return;

    // Per-lane w slice (dims 8t..8t+7) converted once to half2.
    const float4* w4 = reinterpret_cast<const float4*>(w);
    const float4 wv0 = __ldg(w4 + 2 * t);
    const float4 wv1 = __ldg(w4 + 2 * t + 1);
    const __half2 wh0 = __floats2half2_rn(wv0.x, wv0.y);
    const __half2 wh1 = __floats2half2_rn(wv0.z, wv0.w);
    const __half2 wh2 = __floats2half2_rn(wv1.x, wv1.y);
    const __half2 wh3 = __floats2half2_rn(wv1.z, wv1.w);
    const float   bb  = __ldg(bia);

    // Coalesced sorted-edge loads; invalid lanes duplicate slot_base's edge.
    const bool lvalid = (lane < nvalid);
    const int  lslot  = lvalid ? (slot_base + lane) : slot_base;
    const int  ridx   = g_sr[lslot];    // all in one 32-node bucket -> L1
    const int  cidx   = g_sc[lslot];
    const int  eid    = g_se[lslot];
    const int  roff   = ridx << 4;      // row start in uint4 units
    const int  coff   = cidx << 4;

    float res = 0.0f;

    #pragma unroll 4
    for (int j = 0; j < 16; ++j) {
        // group g works on warp-edge 2j+g
        const int src = 2 * j + g;
        const int ro = __shfl_sync(0xffffffffu, roff, src);
        const int co = __shfl_sync(0xffffffffu, coff, src);

        const uint4 a = g_xh[ro + t];   // r-side: L1-resident bucket rows
        const uint4 c = g_xh[co + t];   // c-side: random, L2

        // |a - c| in half2 (HABS2 on ALU pipe), 4-term HFMA2 accumulation.
        const __half2 d0 = __habs2(__hsub2(u2h(a.x), u2h(c.x)));
        const __half2 d1 = __habs2(__hsub2(u2h(a.y), u2h(c.y)));
        const __half2 d2 = __habs2(__hsub2(u2h(a.z), u2h(c.z)));
        const __half2 d3 = __habs2(__hsub2(u2h(a.w), u2h(c.w)));

        __half2 p = __hmul2(d0, wh0);
        p = __hfma2(d1, wh1, p);
        p = __hfma2(d2, wh2, p);
        p = __hfma2(d3, wh3, p);

        const float2 pf = __half22float2(p);
        float s = pf.x + pf.y;

        // Reduce within each 16-lane group (2 edges simultaneously), fp32.
        s += __shfl_xor_sync(0xffffffffu, s, 8);
        s += __shfl_xor_sync(0xffffffffu, s, 4);
        s += __shfl_xor_sync(0xffffffffu, s, 2);
        s += __shfl_xor_sync(0xffffffffu, s, 1);

        if (t == j) res = s;    // lane 16g+j holds warp-edge 2j+g
    }

    // Lane L (g,t) holds warp-edge m = 2t+g; fetch that edge's id from
    // lane m and scatter-store.
    const int m    = 2 * t + g;
    const int oeid = __shfl_sync(0xffffffffu, eid, m);
    if (m < nvalid)
        out[oeid] = res + bb;
}

extern "C" void kernel_launch(void* const* d_in, const int* in_sizes, int n_in,
                              void* d_out, int out_size)
{
    const float* x     = (const float*)d_in[0];   // [N_NODES, 128] fp32
    const int*   r_idx = (const int*)d_in[1];     // [E] int32
    const int*   c_idx = (const int*)d_in[2];     // [E] int32
    const float* w     = (const float*)d_in[3];   // [128, 1] fp32
    const float* b     = (const float*)d_in[4];   // [1] fp32
    float*       out   = (float*)d_out;           // [E] fp32

    const int n_edges = in_sizes[1];              // 600000
    int n_nodes = in_sizes[0] / D_FEAT;           // 100000
    if (n_nodes > MAX_NODES) n_nodes = MAX_NODES;

    // 1) fp32 -> fp16 node table
    const int n_vec = n_nodes * (D_FEAT / 8);     // 1.6M uint4
    convert_fp16_kernel<<<(n_vec + 255) / 256, 256>>>(x, n_vec);

    // 2) zero bucket counters
    zero_cnt_kernel<<<(NB + 255) / 256, 256>>>();

    // 3) bucket edges by r>>5
    scatter_kernel<<<(n_edges + 255) / 256, 256>>>(r_idx, c_idx, x, w, b,
                                                   out, n_edges, n_nodes);

    // 4) gather + abs-diff dot over bucketed slots
    const int warps  = NSLOTS / 32;               // 31250
    const int blocks = (warps + 7) / 8;           // 8 warps/block
    edge_abs_dot_kernel<<<blocks, 256>>>(w, b, out);
}

// round 11
// speedup vs baseline: 1.5711x; 1.5711x over previous
#include <cuda_runtime.h>
#include <cuda_fp16.h>
#include <cstdint>

// out[e] = sum_d |x[r[e],d] - x[c[e],d]| * w[d] + b[0]
// N_NODES=100000, N_EDGES=600000, D=128 (indices int32: jax x64 disabled)
//
// R10 (bucket-sort) regressed 2x: scatter pass cost ~27us in scattered
// 32B-sector stores + atomics; reverted. This is R9 (best main kernel,
// 4 L1-lines/edge fp16 gather, half2 math, depth-2 prefetch) with a
// register cap: __launch_bounds__(256,6) -> 42 regs -> 75% occupancy,
// raising in-flight gather lines to cover L2-hit latency (~235cyc).

#define D_FEAT    128
#define MAX_NODES 100000

// fp16 node table: 100000 rows x 128 halves = 16 uint4 per row (256B rows).
__device__ __align__(256) uint4 g_xh[MAX_NODES * (D_FEAT / 8)];

__global__ __launch_bounds__(256)
void convert_fp16_kernel(const float* __restrict__ x, int n_vec)
{
    const int i = blockIdx.x * blockDim.x + threadIdx.x;
    if (i >= n_vec) return;

    const float4* xf = reinterpret_cast<const float4*>(x);
    const float4 f0 = __ldg(xf + 2 * i);
    const float4 f1 = __ldg(xf + 2 * i + 1);

    const __half2 h0 = __floats2half2_rn(f0.x, f0.y);
    const __half2 h1 = __floats2half2_rn(f0.z, f0.w);
    const __half2 h2 = __floats2half2_rn(f1.x, f1.y);
    const __half2 h3 = __floats2half2_rn(f1.z, f1.w);

    uint4 o;
    o.x = *reinterpret_cast<const unsigned int*>(&h0);
    o.y = *reinterpret_cast<const unsigned int*>(&h1);
    o.z = *reinterpret_cast<const unsigned int*>(&h2);
    o.w = *reinterpret_cast<const unsigned int*>(&h3);
    g_xh[i] = o;
}

__device__ __forceinline__ __half2 u2h(unsigned int u)
{
    return *reinterpret_cast<const __half2*>(&u);
}

__global__ __launch_bounds__(256, 6)   // cap regs ~42 -> 6 blocks/SM (75% occ)
void edge_abs_dot_kernel(const int* __restrict__ r_idx,
                         const int* __restrict__ c_idx,
                         const float* __restrict__ w,
                         const float* __restrict__ b,
                         float* __restrict__ out,
                         int n_edges,
                         int n_nodes)
{
    const int lane  = threadIdx.x & 31;
    const int g     = lane >> 4;        // group 0..1 (one edge each)
    const int t     = lane & 15;        // position within group
    const int gwarp = (blockIdx.x * blockDim.x + threadIdx.x) >> 5;
    const int base  = gwarp << 5;       // 32 edges per warp
    if (base >= n_edges) return;

    // Per-lane w slice (dims 8t..8t+7) converted once to half2.
    const float4* w4 = reinterpret_cast<const float4*>(w);
    const float4 wv0 = __ldg(w4 + 2 * t);
    const float4 wv1 = __ldg(w4 + 2 * t + 1);
    const __half2 wh0 = __floats2half2_rn(wv0.x, wv0.y);
    const __half2 wh1 = __floats2half2_rn(wv0.z, wv0.w);
    const __half2 wh2 = __floats2half2_rn(wv1.x, wv1.y);
    const __half2 wh3 = __floats2half2_rn(wv1.z, wv1.w);
    const float   bb  = __ldg(b);

    // Coalesced index preload; pre-scale to uint4-element offsets so the
    // loop does no multiplies (shfl carries the scaled offset).
    const int eload = min(base + lane, n_edges - 1);
    int ridx = __ldg(r_idx + eload);
    int cidx = __ldg(c_idx + eload);
    ridx = min(max(ridx, 0), n_nodes - 1);
    cidx = min(max(cidx, 0), n_nodes - 1);
    const int roff = ridx << 4;         // row start in uint4 units
    const int coff = cidx << 4;

    // Depth-2 software pipeline: iterations j and j+1 in flight.
    uint4 a_cur, c_cur, a_nxt, c_nxt;
    {
        const int s0 = g;                       // j=0: edge base+g
        const int s1 = 2 + g;                   // j=1: edge base+2+g
        const int ro0 = __shfl_sync(0xffffffffu, roff, s0);
        const int co0 = __shfl_sync(0xffffffffu, coff, s0);
        const int ro1 = __shfl_sync(0xffffffffu, roff, s1);
        const int co1 = __shfl_sync(0xffffffffu, coff, s1);
        a_cur = g_xh[ro0 + t];
        c_cur = g_xh[co0 + t];
        a_nxt = g_xh[ro1 + t];
        c_nxt = g_xh[co1 + t];
    }

    float res = 0.0f;

    #pragma unroll 8
    for (int j = 0; j < 16; ++j) {
        const uint4 a = a_cur;
        const uint4 c = c_cur;
        a_cur = a_nxt;
        c_cur = c_nxt;
        if (j < 14) {
            const int src = 2 * (j + 2) + g;
            const int ro = __shfl_sync(0xffffffffu, roff, src);
            const int co = __shfl_sync(0xffffffffu, coff, src);
            a_nxt = g_xh[ro + t];
            c_nxt = g_xh[co + t];
        }

        // |a - c| in half2 (HABS2 on ALU pipe), 4-term HFMA2 accumulation.
        const __half2 d0 = __habs2(__hsub2(u2h(a.x), u2h(c.x)));
        const __half2 d1 = __habs2(__hsub2(u2h(a.y), u2h(c.y)));
        const __half2 d2 = __habs2(__hsub2(u2h(a.z), u2h(c.z)));
        const __half2 d3 = __habs2(__hsub2(u2h(a.w), u2h(c.w)));

        __half2 p = __hmul2(d0, wh0);
        p = __hfma2(d1, wh1, p);
        p = __hfma2(d2, wh2, p);
        p = __hfma2(d3, wh3, p);

        const float2 pf = __half22float2(p);
        float s = pf.x + pf.y;

        // Reduce within each 16-lane group (2 edges simultaneously), fp32.
        s += __shfl_xor_sync(0xffffffffu, s, 8);
        s += __shfl_xor_sync(0xffffffffu, s, 4);
        s += __shfl_xor_sync(0xffffffffu, s, 2);
        s += __shfl_xor_sync(0xffffffffu, s, 1);

        if (t == j) res = s;    // lane 16g+j holds edge base+2j+g
    }

    // Lane L (g=L>>4, t=L&15) stores edge base + 2t + g.
    // All 32 targets lie in one 128B line -> single store wavefront.
    const int estore = base + 2 * t + g;
    if (estore < n_edges)
        out[estore] = res + bb;
}

extern "C" void kernel_launch(void* const* d_in, const int* in_sizes, int n_in,
                              void* d_out, int out_size)
{
    const float* x     = (const float*)d_in[0];   // [N_NODES, 128] fp32
    const int*   r_idx = (const int*)d_in[1];     // [E] int32
    const int*   c_idx = (const int*)d_in[2];     // [E] int32
    const float* w     = (const float*)d_in[3];   // [128, 1] fp32
    const float* b     = (const float*)d_in[4];   // [1] fp32
    float*       out   = (float*)d_out;           // [E] fp32

    const int n_edges = in_sizes[1];              // 600000
    int n_nodes = in_sizes[0] / D_FEAT;           // 100000
    if (n_nodes > MAX_NODES) n_nodes = MAX_NODES;

    // 1) fp32 -> fp16 node table (each thread emits one uint4 = 8 halves)
    const int n_vec = n_nodes * (D_FEAT / 8);     // 1.6M
    convert_fp16_kernel<<<(n_vec + 255) / 256, 256>>>(x, n_vec);

    // 2) edge gather + abs-diff dot
    const int threads = 256;                      // 8 warps/block
    const int edges_per_block = (threads / 32) * 32;   // 256 edges
    const int blocks = (n_edges + edges_per_block - 1) / edges_per_block;
    edge_abs_dot_kernel<<<blocks, threads>>>(r_idx, c_idx, w, b, out,
                                             n_edges, n_nodes);
}

// round 12
// speedup vs baseline: 1.9836x; 1.2626x over previous
#include <cuda_runtime.h>
#include <cuda_fp16.h>
#include <cstdint>

// out[e] = sum_d |x[r[e],d] - x[c[e],d]| * w[d] + b[0]
// N_NODES=100000, N_EDGES=600000, D=128 (indices int32: jax x64 disabled)
//
// CONVERGED CONFIG (R9, restored after R10/R11 regressions):
//   1) convert: fp32 -> fp16 node table in __device__ scratch
//      (77MB LTS traffic, ~6us, at LTS cap)
//   2) gather: 16 lanes/edge, 4 L1-lines/edge, half2 math, depth-2
//      prefetch (307MB LTS traffic, ~25us, at LTS cap ~12.4TB/s)
// Total LTS bytes 391MB == measured 31.2us at the chip-wide LTS ceiling.
// Byte-reduction alternatives (12-bit tables, bucketing, w-folding) were
// evaluated and are either issue-bound or exceed the 1e-3 error budget.

#define D_FEAT    128
#define MAX_NODES 100000

// fp16 node table: 100000 rows x 128 halves = 16 uint4 per row (256B rows).
__device__ __align__(256) uint4 g_xh[MAX_NODES * (D_FEAT / 8)];

__global__ __launch_bounds__(256)
void convert_fp16_kernel(const float* __restrict__ x, int n_vec)
{
    const int i = blockIdx.x * blockDim.x + threadIdx.x;
    if (i >= n_vec) return;

    const float4* xf = reinterpret_cast<const float4*>(x);
    const float4 f0 = __ldg(xf + 2 * i);
    const float4 f1 = __ldg(xf + 2 * i + 1);

    const __half2 h0 = __floats2half2_rn(f0.x, f0.y);
    const __half2 h1 = __floats2half2_rn(f0.z, f0.w);
    const __half2 h2 = __floats2half2_rn(f1.x, f1.y);
    const __half2 h3 = __floats2half2_rn(f1.z, f1.w);

    uint4 o;
    o.x = *reinterpret_cast<const unsigned int*>(&h0);
    o.y = *reinterpret_cast<const unsigned int*>(&h1);
    o.z = *reinterpret_cast<const unsigned int*>(&h2);
    o.w = *reinterpret_cast<const unsigned int*>(&h3);
    g_xh[i] = o;
}

__device__ __forceinline__ __half2 u2h(unsigned int u)
{
    return *reinterpret_cast<const __half2*>(&u);
}

__global__ __launch_bounds__(256)
void edge_abs_dot_kernel(const int* __restrict__ r_idx,
                         const int* __restrict__ c_idx,
                         const float* __restrict__ w,
                         const float* __restrict__ b,
                         float* __restrict__ out,
                         int n_edges,
                         int n_nodes)
{
    const int lane  = threadIdx.x & 31;
    const int g     = lane >> 4;        // group 0..1 (one edge each)
    const int t     = lane & 15;        // position within group
    const int gwarp = (blockIdx.x * blockDim.x + threadIdx.x) >> 5;
    const int base  = gwarp << 5;       // 32 edges per warp
    if (base >= n_edges) return;

    // Per-lane w slice (dims 8t..8t+7) converted once to half2.
    const float4* w4 = reinterpret_cast<const float4*>(w);
    const float4 wv0 = __ldg(w4 + 2 * t);
    const float4 wv1 = __ldg(w4 + 2 * t + 1);
    const __half2 wh0 = __floats2half2_rn(wv0.x, wv0.y);
    const __half2 wh1 = __floats2half2_rn(wv0.z, wv0.w);
    const __half2 wh2 = __floats2half2_rn(wv1.x, wv1.y);
    const __half2 wh3 = __floats2half2_rn(wv1.z, wv1.w);
    const float   bb  = __ldg(b);

    // Coalesced index preload; pre-scale to uint4-element offsets so the
    // loop does no multiplies (shfl carries the scaled offset).
    const int eload = min(base + lane, n_edges - 1);
    int ridx = __ldg(r_idx + eload);
    int cidx = __ldg(c_idx + eload);
    ridx = min(max(ridx, 0), n_nodes - 1);
    cidx = min(max(cidx, 0), n_nodes - 1);
    const int roff = ridx << 4;         // row start in uint4 units
    const int coff = cidx << 4;

    // Depth-2 software pipeline: iterations j and j+1 in flight.
    uint4 a_cur, c_cur, a_nxt, c_nxt;
    {
        const int s0 = g;                       // j=0: edge base+g
        const int s1 = 2 + g;                   // j=1: edge base+2+g
        const int ro0 = __shfl_sync(0xffffffffu, roff, s0);
        const int co0 = __shfl_sync(0xffffffffu, coff, s0);
        const int ro1 = __shfl_sync(0xffffffffu, roff, s1);
        const int co1 = __shfl_sync(0xffffffffu, coff, s1);
        a_cur = g_xh[ro0 + t];
        c_cur = g_xh[co0 + t];
        a_nxt = g_xh[ro1 + t];
        c_nxt = g_xh[co1 + t];
    }

    float res = 0.0f;

    #pragma unroll 4
    for (int j = 0; j < 16; ++j) {
        const uint4 a = a_cur;
        const uint4 c = c_cur;
        a_cur = a_nxt;
        c_cur = c_nxt;
        if (j < 14) {
            const int src = 2 * (j + 2) + g;
            const int ro = __shfl_sync(0xffffffffu, roff, src);
            const int co = __shfl_sync(0xffffffffu, coff, src);
            a_nxt = g_xh[ro + t];
            c_nxt = g_xh[co + t];
        }

        // |a - c| in half2 (HABS2 on ALU pipe), 4-term HFMA2 accumulation.
        const __half2 d0 = __habs2(__hsub2(u2h(a.x), u2h(c.x)));
        const __half2 d1 = __habs2(__hsub2(u2h(a.y), u2h(c.y)));
        const __half2 d2 = __habs2(__hsub2(u2h(a.z), u2h(c.z)));
        const __half2 d3 = __habs2(__hsub2(u2h(a.w), u2h(c.w)));

        __half2 p = __hmul2(d0, wh0);
        p = __hfma2(d1, wh1, p);
        p = __hfma2(d2, wh2, p);
        p = __hfma2(d3, wh3, p);

        const float2 pf = __half22float2(p);
        float s = pf.x + pf.y;

        // Reduce within each 16-lane group (2 edges simultaneously), fp32.
        s += __shfl_xor_sync(0xffffffffu, s, 8);
        s += __shfl_xor_sync(0xffffffffu, s, 4);
        s += __shfl_xor_sync(0xffffffffu, s, 2);
        s += __shfl_xor_sync(0xffffffffu, s, 1);

        if (t == j) res = s;    // lane 16g+j holds edge base+2j+g
    }

    // Lane L (g=L>>4, t=L&15) stores edge base + 2t + g.
    // All 32 targets lie in one 128B line -> single store wavefront.
    const int estore = base + 2 * t + g;
    if (estore < n_edges)
        out[estore] = res + bb;
}

extern "C" void kernel_launch(void* const* d_in, const int* in_sizes, int n_in,
                              void* d_out, int out_size)
{
    const float* x     = (const float*)d_in[0];   // [N_NODES, 128] fp32
    const int*   r_idx = (const int*)d_in[1];     // [E] int32
    const int*   c_idx = (const int*)d_in[2];     // [E] int32
    const float* w     = (const float*)d_in[3];   // [128, 1] fp32
    const float* b     = (const float*)d_in[4];   // [1] fp32
    float*       out   = (float*)d_out;           // [E] fp32

    const int n_edges = in_sizes[1];              // 600000
    int n_nodes = in_sizes[0] / D_FEAT;           // 100000
    if (n_nodes > MAX_NODES) n_nodes = MAX_NODES;

    // 1) fp32 -> fp16 node table (each thread emits one uint4 = 8 halves)
    const int n_vec = n_nodes * (D_FEAT / 8);     // 1.6M
    convert_fp16_kernel<<<(n_vec + 255) / 256, 256>>>(x, n_vec);

    // 2) edge gather + abs-diff dot
    const int threads = 256;                      // 8 warps/block
    const int edges_per_block = (threads / 32) * 32;   // 256 edges
    const int blocks = (n_edges + edges_per_block - 1) / edges_per_block;
    edge_abs_dot_kernel<<<blocks, threads>>>(r_idx, c_idx, w, b, out,
                                             n_edges, n_nodes);
}